// round 5
// baseline (speedup 1.0000x reference)
#include <cuda_runtime.h>
#include <float.h>
#include <stdint.h>

#define MAXN 8192

// Scratch (no device allocations allowed). Written and read only by block 0,
// ordered by __syncthreads within that block.
__device__ int g_leaf[MAXN];

// ---------------------------------------------------------------------------
// Fused kernel.
//   block 0            : prologue (leaf compaction + retrieve_indices)
//   blocks 1..n        : row i = blockIdx.x - 1 of tree_mask / masked_scores
__global__ void __launch_bounds__(256) fused_kernel(
    const int* __restrict__ mask_index,   // (n-1,) int32 parents
    const int* __restrict__ tpi,          // (n,)   int32 tree_position_ids
    const float* __restrict__ scores,     // (n,n)  float32
    float* __restrict__ outMask,          // (n,n)  float32 (bool as 0/1)
    float* __restrict__ outRI,            // (n,depth) float32
    float* __restrict__ outScores,        // (n,n)  float32
    int n, int depth)
{
    __shared__ unsigned bits[MAXN / 32];   // 1 KB: row bitset OR noleaf bitset
    __shared__ int warpsum[8];

    const int tid = threadIdx.x;
    const int T = n - 1;

    if (blockIdx.x == 0) {
        // ================= PROLOGUE BLOCK =================
        const int nw = (n + 31) >> 5;
        for (int w = tid; w < MAXN / 32; w += 256) bits[w] = 0;
        for (int k = tid; k < n; k += 256) g_leaf[k] = -1;
        __syncthreads();

        // 1) noleaf bitset: any node appearing as a parent
        for (int t = tid; t < T; t += 256) {
            int v = mask_index[t];
            if (v >= 0 && v < n) atomicOr(&bits[v >> 5], 1u << (v & 31));
        }
        __syncthreads();

        // 2) ordered leaf compaction via popcount scan (256 words, 256 threads)
        unsigned leafbits = 0;
        int c = 0;
        {
            int base = tid * 32;
            unsigned vm = 0;
            if (base < n) {
                int rem = n - base;
                vm = (rem >= 32) ? 0xFFFFFFFFu : ((1u << rem) - 1u);
            }
            unsigned w = (tid < nw) ? bits[tid] : 0u;
            leafbits = (~w) & vm;            // leaf = not a parent
            c = __popc(leafbits);
        }
        // inclusive warp scan of c
        int lane = tid & 31, wrp = tid >> 5;
        int s = c;
        #pragma unroll
        for (int o = 1; o < 32; o <<= 1) {
            int v = __shfl_up_sync(0xFFFFFFFFu, s, o);
            if (lane >= o) s += v;
        }
        if (lane == 31) warpsum[wrp] = s;
        __syncthreads();
        if (wrp == 0 && lane < 8) {
            int v = warpsum[lane];
            #pragma unroll
            for (int o = 1; o < 8; o <<= 1) {
                int u = __shfl_up_sync(0xFFu, v, o);
                if (lane >= o) v += u;
            }
            warpsum[lane] = v;
        }
        __syncthreads();
        int excl = s - c + (wrp ? warpsum[wrp - 1] : 0);
        {
            unsigned lb = leafbits;
            int pos = excl;
            while (lb) {
                int b = __ffs(lb) - 1;
                lb &= lb - 1;
                if (pos < n) g_leaf[pos] = tid * 32 + b;
                pos++;
            }
        }
        __syncthreads();

        // 3) retrieve_indices: parent-chain walk per leaf slot
        if (depth > 0) {
            for (int r = tid; r < n; r += 256) {
                int cur = g_leaf[r];
                long long base = (long long)r * depth;
                for (int d = 0; d < depth; d++) {
                    int cc  = cur < 0 ? 0 : cur;
                    int pos = tpi[cc];
                    outRI[base + d] = (cur >= 0 && pos >= d) ? (float)cur : -1.0f;
                    cur = (cur > 0) ? mask_index[cur - 1] : -1;
                }
            }
        }
        return;
    }

    // ================= ROW BLOCKS =================
    const int i = blockIdx.x - 1;            // row index
    const int nw = (n + 31) >> 5;
    for (int w = tid; w < nw; w += 256) bits[w] = 0;
    __syncthreads();

    if (tid == 0) {
        bits[0] |= 1u;                       // column 0 always true
        bits[i >> 5] |= 1u << (i & 31);      // diagonal
        int cur = i;
        #pragma unroll 1
        for (int s2 = 0; s2 < 32 && cur > 0; s2++) {  // ancestor chain
            int p = mask_index[cur - 1];
            if (p < 0 || p >= n) break;
            bits[p >> 5] |= 1u << (p & 31);
            cur = p;
        }
    }
    __syncthreads();

    const float NEG = -FLT_MAX;              // jnp.finfo(float32).min
    const long long rowOff = (long long)i * n;
    const int stride4 = 256 * 4;

    int j = tid * 4;
    for (; j + 3 < n; j += stride4) {
        unsigned b = (bits[j >> 5] >> (j & 31)) & 0xFu;  // (j&31) multiple of 4
        float4 m = make_float4(0.f, 0.f, 0.f, 0.f);
        float4 sc = make_float4(NEG, NEG, NEG, NEG);
        if (b) {
            if (b & 1u) { m.x = 1.f; sc.x = scores[rowOff + j];     }
            if (b & 2u) { m.y = 1.f; sc.y = scores[rowOff + j + 1]; }
            if (b & 4u) { m.z = 1.f; sc.z = scores[rowOff + j + 2]; }
            if (b & 8u) { m.w = 1.f; sc.w = scores[rowOff + j + 3]; }
        }
        __stcs(reinterpret_cast<float4*>(outMask + rowOff + j), m);
        __stcs(reinterpret_cast<float4*>(outScores + rowOff + j), sc);
    }
    for (; j < n; j++) {                      // tail (not hit for n=8192)
        unsigned on = (bits[j >> 5] >> (j & 31)) & 1u;
        outMask[rowOff + j]   = on ? 1.f : 0.f;
        outScores[rowOff + j] = on ? scores[rowOff + j] : NEG;
    }
}

// ---------------------------------------------------------------------------
extern "C" void kernel_launch(void* const* d_in, const int* in_sizes, int n_in,
                              void* d_out, int out_size) {
    // Identify inputs by element count (robust to scalar inputs / reordering):
    //   scores: n*n (largest), tpi: n, mask_index: n-1
    int scoresIdx = 0;
    long long maxSz = -1;
    for (int k = 0; k < n_in; k++)
        if ((long long)in_sizes[k] > maxSz) { maxSz = in_sizes[k]; scoresIdx = k; }
    int n = 1;
    while ((long long)(n + 1) * (n + 1) <= maxSz) n++;   // n = sqrt(maxSz)
    const int T = n - 1;

    int miIdx = -1, tpiIdx = -1;
    for (int k = 0; k < n_in; k++) {
        if (k == scoresIdx) continue;
        if (in_sizes[k] == T && miIdx < 0) miIdx = k;
        else if (in_sizes[k] == n && tpiIdx < 0) tpiIdx = k;
    }
    if (miIdx < 0) miIdx = 0;
    if (tpiIdx < 0) tpiIdx = (miIdx == 1) ? 0 : 1;

    const int*   mask_index = (const int*)d_in[miIdx];
    const int*   tpi        = (const int*)d_in[tpiIdx];
    const float* scores     = (const float*)d_in[scoresIdx];

    const long long nn = (long long)n * n;
    // out = [tree_mask (n*n) | retrieve_indices (n*depth) | masked_scores (n*n)]
    int depth = (int)(((long long)out_size - 2 * nn) / n);
    if (depth < 0) depth = 0;

    float* outMask   = (float*)d_out;
    float* outRI     = outMask + nn;
    float* outScores = outRI + (long long)n * depth;

    fused_kernel<<<n + 1, 256>>>(mask_index, tpi, scores,
                                 outMask, outRI, outScores, n, depth);
}